// round 1
// baseline (speedup 1.0000x reference)
#include <cuda_runtime.h>
#include <math.h>

// Problem constants
#define GRID   128      // persistent CTAs (<= SM count, 1 per SM)
#define NT     512      // threads per CTA
#define COLS   16       // output columns per CTA (128*16 = 2048)
#define H      2048
#define D      16
#define TMAX   4096
#define OUTN   128
#define WPT    64       // weights per thread (2048 / 32 k-segments)
#define HPITCH 68       // 64 + 4 pad floats per k-segment row in SMEM
#define WSTRIDE ((size_t)2049 * 2048)

// Persistent device state (allowed: __device__ globals, no allocation)
__device__ unsigned g_bar;
__device__ __align__(16) float g_h[2][H];
__device__ float g_logits[OUTN];

__global__ void awk_reset_kernel() { g_bar = 0u; }

// Grid-wide barrier: fence + relaxed atomic arrive, acquire-spin by thread 0.
__device__ __forceinline__ void grid_bar(int tid, unsigned target) {
    __syncthreads();
    if (tid == 0) {
        __threadfence();                 // release: order prior stores (incl. CTA peers via bar.sync chain)
        atomicAdd(&g_bar, 1u);
        unsigned v;
        do {
            asm volatile("ld.acquire.gpu.b32 %0, [%1];" : "=r"(v) : "l"(&g_bar) : "memory");
        } while (v < target);
    }
    __syncthreads();                     // propagate acquire CTA-wide
}

extern __shared__ float sm[];

__global__ __launch_bounds__(NT, 1)
void awk_kernel(const float* __restrict__ x_in,   // [4096]
                const float* __restrict__ h0,     // [2048]
                const float* __restrict__ Wg,     // [16, 2049, 2048]
                const float* __restrict__ bg,     // [16, 2048]
                const float* __restrict__ Wo,     // [2048, 128]
                const float* __restrict__ bo,     // [128]
                const int*   __restrict__ markers,// [16]
                float* __restrict__ outp, int out_size)
{
    // SMEM layout
    float* x_sm   = sm;                          // 4096
    float* h_sm   = x_sm + TMAX;                 // 32 * 68 = 2176
    float* wstage = h_sm + 32 * HPITCH;          // 32896 (2048*16 + pads)
    float* red_sm = wstage + 32896;              // 256
    int*   cum_sm = (int*)(red_sm + 256);        // 17 (+pad)

    const int tid   = threadIdx.x;
    const int bid   = blockIdx.x;
    const int c     = tid & 15;     // column within CTA
    const int s     = tid >> 4;     // k-segment 0..31 (64 k-values each)
    const int jbase = bid * COLS;

    // Preload input scalars; cumsum markers; init h buffer 0
    for (int i = tid; i < TMAX; i += NT) x_sm[i] = x_in[i];
    if (tid == 0) {
        int a = 0;
        for (int l = 0; l < D; l++) { a += markers[l]; cum_sm[l] = a; }
        cum_sm[D] = (a < TMAX) ? a : TMAX;
    }
    if (tid < COLS) g_h[0][jbase + tid] = h0[jbase + tid];
    __syncthreads();
    const int S = cum_sm[D];

    unsigned target = GRID;
    grid_bar(tid, target); target += GRID;   // init h visible everywhere

    float w[WPT];
    float w0 = 0.f, bb = 0.f;
    int layer = 0;
    int next_b = 0;

    for (int step = 0; step < S; ++step) {
        // ---- layer switch: refill register-resident weights (uniform across grid) ----
        if (step == next_b) {
            while (step >= cum_sm[layer]) layer++;
            next_b = cum_sm[layer];
            __syncthreads();
            const float* Wl = Wg + (size_t)layer * WSTRIDE + 2048;  // skip x-row
            int k0 = tid >> 2, cq = tid & 3;
            #pragma unroll 4
            for (int k = k0; k < H; k += 128) {
                float4 v = *(const float4*)(Wl + (size_t)k * 2048 + jbase + cq * 4);
                *(float4*)(wstage + k * 16 + cq * 4 + 4 * (k >> 6)) = v;
            }
            __syncthreads();
            #pragma unroll
            for (int u = 0; u < WPT; u++)
                w[u] = wstage[(s * WPT + u) * 16 + c + 4 * s];
            if (tid < COLS) {
                w0 = Wg[(size_t)layer * WSTRIDE + jbase + tid];   // x-row weight
                bb = bg[layer * H + jbase + tid];
            }
            __syncthreads();
        }

        // ---- broadcast h into SMEM (padded layout) ----
        {
            float4 v = *(const float4*)(g_h[step & 1] + tid * 4);
            int i = tid * 4;
            *(float4*)(h_sm + (i >> 6) * HPITCH + (i & 63)) = v;
        }
        __syncthreads();

        // ---- partial dot: 64 MACs/thread, 4 independent chains ----
        float a0 = 0.f, a1 = 0.f, a2 = 0.f, a3 = 0.f;
        const float* hp = h_sm + s * HPITCH;
        #pragma unroll
        for (int q = 0; q < WPT / 4; q++) {
            float4 hv = *(const float4*)(hp + 4 * q);
            a0 = fmaf(hv.x, w[4 * q + 0], a0);
            a1 = fmaf(hv.y, w[4 * q + 1], a1);
            a2 = fmaf(hv.z, w[4 * q + 2], a2);
            a3 = fmaf(hv.w, w[4 * q + 3], a3);
        }
        float acc = (a0 + a1) + (a2 + a3);

        // pair-combine segments (s, s^1) within warp, then cross-warp via SMEM
        acc += __shfl_xor_sync(0xffffffffu, acc, 16);
        if ((tid & 16) == 0) red_sm[(tid >> 5) * 16 + c] = acc;
        __syncthreads();

        if (tid < COLS) {
            float v = 0.f;
            #pragma unroll
            for (int wi = 0; wi < 16; wi++) v += red_sm[wi * 16 + tid];
            v = fmaf(x_sm[step], w0, v) + bb;
            v = fmaxf(v, 0.f);
            g_h[(step + 1) & 1][jbase + tid] = v;
        }

        grid_bar(tid, target); target += GRID;
    }

    // ---- epilogue: final h into SMEM ----
    {
        float4 v = *(const float4*)(g_h[S & 1] + tid * 4);
        int i = tid * 4;
        *(float4*)(h_sm + (i >> 6) * HPITCH + (i & 63)) = v;
    }
    __syncthreads();

    // logit for output o = bid  (GRID == 128 == OUTN)
    float p = 0.f;
    #pragma unroll
    for (int r = 0; r < H / NT; r++) {
        int i = r * NT + tid;
        p += h_sm[(i >> 6) * HPITCH + (i & 63)] * Wo[(size_t)i * OUTN + bid];
    }
    p += __shfl_xor_sync(0xffffffffu, p, 16);
    p += __shfl_xor_sync(0xffffffffu, p, 8);
    p += __shfl_xor_sync(0xffffffffu, p, 4);
    p += __shfl_xor_sync(0xffffffffu, p, 2);
    p += __shfl_xor_sync(0xffffffffu, p, 1);
    if ((tid & 31) == 0) red_sm[tid >> 5] = p;
    __syncthreads();
    if (tid == 0) {
        float v = 0.f;
        for (int wi = 0; wi < 16; wi++) v += red_sm[wi];
        g_logits[bid] = v + bo[bid];
    }
    grid_bar(tid, target); target += GRID;

    // hidden part of output
    int hoff = -1;
    if (out_size >= OUTN + H) hoff = OUTN;
    else if (out_size == H)   hoff = 0;
    if (hoff >= 0 && tid < COLS) {
        int j = jbase + tid;
        outp[hoff + j] = h_sm[(j >> 6) * HPITCH + (j & 63)];
    }

    // log_softmax of the 128 logits, CTA 0 only
    if (bid == 0 && out_size != H) {
        float v = (tid < OUTN) ? g_logits[tid] : -INFINITY;
        float m = v;
        m = fmaxf(m, __shfl_xor_sync(0xffffffffu, m, 16));
        m = fmaxf(m, __shfl_xor_sync(0xffffffffu, m, 8));
        m = fmaxf(m, __shfl_xor_sync(0xffffffffu, m, 4));
        m = fmaxf(m, __shfl_xor_sync(0xffffffffu, m, 2));
        m = fmaxf(m, __shfl_xor_sync(0xffffffffu, m, 1));
        if ((tid & 31) == 0) red_sm[tid >> 5] = m;
        __syncthreads();
        if (tid == 0) {
            float mm = red_sm[0];
            for (int wi = 1; wi < 16; wi++) mm = fmaxf(mm, red_sm[wi]);
            red_sm[32] = mm;
        }
        __syncthreads();
        float mm = red_sm[32];
        float e = (tid < OUTN) ? expf(v - mm) : 0.f;
        e += __shfl_xor_sync(0xffffffffu, e, 16);
        e += __shfl_xor_sync(0xffffffffu, e, 8);
        e += __shfl_xor_sync(0xffffffffu, e, 4);
        e += __shfl_xor_sync(0xffffffffu, e, 2);
        e += __shfl_xor_sync(0xffffffffu, e, 1);
        __syncthreads();
        if ((tid & 31) == 0) red_sm[tid >> 5] = e;
        __syncthreads();
        if (tid == 0) {
            float ss = 0.f;
            for (int wi = 0; wi < 16; wi++) ss += red_sm[wi];
            red_sm[33] = logf(ss);
        }
        __syncthreads();
        if (tid < OUTN) outp[tid] = v - mm - red_sm[33];
    }
}

extern "C" void kernel_launch(void* const* d_in, const int* in_sizes, int n_in,
                              void* d_out, int out_size) {
    const float* x  = (const float*)d_in[0];
    const float* h0 = (const float*)d_in[1];
    const float* W  = (const float*)d_in[2];
    const float* b  = (const float*)d_in[3];
    const float* Wo = (const float*)d_in[4];
    const float* bo = (const float*)d_in[5];
    const int*   mk = (const int*)d_in[6];

    size_t smem = (size_t)(TMAX + 32 * HPITCH + 32896 + 256) * sizeof(float) + 32 * sizeof(int);
    cudaFuncSetAttribute(awk_kernel, cudaFuncAttributeMaxDynamicSharedMemorySize, (int)smem);

    awk_reset_kernel<<<1, 1>>>();
    awk_kernel<<<GRID, NT, smem>>>(x, h0, W, b, Wo, bo, mk, (float*)d_out, out_size);
}